// round 15
// baseline (speedup 1.0000x reference)
#include <cuda_runtime.h>
#include <math.h>
#include <stdint.h>

// Problem constants (inputs: [8192, 64] fp32)
#define S        8192
#define E        64
#define CAP      256              // floor(2.0 * 8192 / 64) = 256
#define ROW      (E * CAP)        // 16384 floats per token row
#define CB_ELEMS (S * E * CAP)    // 134,217,728
#define NCHUNK   (S / 32)         // 256 chunks of 32 tokens (warp-ballot grain)
#define RBLOCKS  32               // routing blocks, 256 tokens each

// -------- allocation-free scratch (device globals) --------
__device__ int   g_top1[S];
__device__ int   g_top2[S];
__device__ float g_w1[S];
__device__ float g_w2[S];
__device__ int   g_hist1[NCHUNK * E];
__device__ int   g_hist2[NCHUNK * E];
__device__ int   g_off1[NCHUNK * E];   // exclusive cumsum over chunks
__device__ int   g_off2[NCHUNK * E];
__device__ int   g_total1[E];
__device__ int   g_done;               // routing blocks completed
__device__ volatile int g_flag;        // scan results ready
__device__ int   g_exit;               // blocks past their spin (for reset)

// ---------------------------------------------------------------------------
// Single fused kernel. grid = S blocks x 256 threads.
//  Phase A (bid < 32): thread-per-token routing (softmax + top1/top2, argmax
//    tie-break = first index) + per-warp (=32-token chunk) histograms. The
//    last routing block performs the per-expert exclusive scan and releases
//    g_flag.
//  Phase B (all blocks): stream zeros over own token row, spin on g_flag
//    (already set by then), ballot-rank + patch the <=2 nonzeros.
//  Exit: last block past the spin resets flag state for the next replay.
// ---------------------------------------------------------------------------
__global__ void __launch_bounds__(256) mega_kernel(const float* __restrict__ in,
                                                   float* __restrict__ out,
                                                   int has_mask) {
    const int tid = threadIdx.x;
    const int bid = blockIdx.x;

    // ================= Phase A: routing + hist + scan =================
    if (bid < RBLOCKS) {
        __shared__ int h1[8 * E];
        __shared__ int h2[8 * E];
        for (int i = tid; i < 8 * E; i += 256) { h1[i] = 0; h2[i] = 0; }
        __syncthreads();

        const int tok = bid * 256 + tid;
        const float4* r4 = (const float4*)(in + (size_t)tok * E);

        // pass 1: online top-2 (strict > keeps first occurrence, matching
        // jnp.argmax; a duplicate of the max lands in slot 2 — also correct)
        float v1 = -INFINITY, v2 = -INFINITY;
        int   i1 = 0,         i2 = 0;
#pragma unroll
        for (int i = 0; i < 16; i++) {
            float4 v = r4[i];
            float vv[4] = {v.x, v.y, v.z, v.w};
#pragma unroll
            for (int k = 0; k < 4; k++) {
                float x = vv[k]; int j = 4 * i + k;
                if (x > v1)      { v2 = v1; i2 = i1; v1 = x; i1 = j; }
                else if (x > v2) { v2 = x;  i2 = j; }
            }
        }
        // pass 2: softmax denominator (row is 256B, L1-hot on reload)
        float sum = 0.f;
#pragma unroll
        for (int i = 0; i < 16; i++) {
            float4 v = r4[i];
            sum += expf(v.x - v1) + expf(v.y - v1)
                 + expf(v.z - v1) + expf(v.w - v1);
        }

        g_top1[tok] = i1;
        g_top2[tok] = i2;
        g_w1[tok]   = 1.0f / sum;
        g_w2[tok]   = expf(v2 - v1) / sum;

        // per-warp (= per-32-token-chunk) histogram
        int wid = tid >> 5;
        atomicAdd(&h1[wid * E + i1], 1);
        atomicAdd(&h2[wid * E + i2], 1);
        __syncthreads();
        for (int i = tid; i < 8 * E; i += 256) {
            g_hist1[(size_t)bid * 8 * E + i] = h1[i];
            g_hist2[(size_t)bid * 8 * E + i] = h2[i];
        }
        __threadfence();
        __syncthreads();

        __shared__ int lastflag;
        if (tid == 0) lastflag = (atomicAdd(&g_done, 1) == RBLOCKS - 1);
        __syncthreads();

        if (lastflag) {           // last routing block: per-expert scan
            if (tid < E) {
                const int e = tid;
                int r1 = 0, r2 = 0;
                for (int c = 0; c < NCHUNK; c++) {
                    g_off1[c * E + e] = r1;  r1 += g_hist1[c * E + e];
                    g_off2[c * E + e] = r2;  r2 += g_hist2[c * E + e];
                }
                g_total1[e] = r1;
            }
            __syncthreads();
            __threadfence();
            if (tid == 0) { g_done = 0; g_flag = 1; }   // release
        }
    }

    // ================= Phase B: zero own row =================
    const int tok = bid;
    size_t wbase = (size_t)tok * ROW;
    float4* w4 = (float4*)(out + wbase);
    float4* m4 = (float4*)(out + (size_t)CB_ELEMS + wbase);
    const float4 z = make_float4(0.f, 0.f, 0.f, 0.f);

    if (has_mask) {
#pragma unroll
        for (int i = 0; i < ROW / 4 / 256; i++) {       // 16 iters
            __stcs(&w4[i * 256 + tid], z);
            __stcs(&m4[i * 256 + tid], z);
        }
    } else {
#pragma unroll
        for (int i = 0; i < ROW / 4 / 256; i++)
            __stcs(&w4[i * 256 + tid], z);
    }

    // ---- acquire scan results (flag is set ~8us in; zeroing wave ~18us) ----
    if (tid == 0) { while (g_flag == 0) { } }
    __syncthreads();        // also orders the zeros before the patch below
    __threadfence();

    // ================= patch <=2 nonzeros (warp 0) =================
    if (tid < 32) {
        int lane  = tid;
        int chunk = tok >> 5;
        int tpos  = tok & 31;
        unsigned ltmask = (1u << tpos) - 1u;

        int t1 = g_top1[(chunk << 5) + lane];
        int t2 = g_top2[(chunk << 5) + lane];
        int e1 = __shfl_sync(0xffffffffu, t1, tpos);
        int e2 = __shfl_sync(0xffffffffu, t2, tpos);

        unsigned m1 = __ballot_sync(0xffffffffu, t1 == e1);
        unsigned m2 = __ballot_sync(0xffffffffu, t2 == e2);

        if (lane == 0) {
            int r1 = g_off1[chunk * E + e1] + __popc(m1 & ltmask);
            int r2 = g_total1[e2] + g_off2[chunk * E + e2] + __popc(m2 & ltmask);
            if (r1 < CAP) {
                size_t o = wbase + (size_t)e1 * CAP + r1;
                out[o] = g_w1[tok];
                if (has_mask) out[(size_t)CB_ELEMS + o] = 1.0f;
            }
            if (r2 < CAP) {
                size_t o = wbase + (size_t)e2 * CAP + r2;
                out[o] = g_w2[tok];
                if (has_mask) out[(size_t)CB_ELEMS + o] = 1.0f;
            }
        }
    }

    // ================= exit: reset flag state for next replay =================
    __syncthreads();
    if (tid == 0) {
        __threadfence();
        int v = atomicAdd(&g_exit, 1);
        if (v == S - 1) {       // every block has passed its spin
            g_exit = 0;
            g_flag = 0;
        }
    }
}

// ---------------------------------------------------------------------------
extern "C" void kernel_launch(void* const* d_in, const int* in_sizes, int n_in,
                              void* d_out, int out_size) {
    const float* in  = (const float*)d_in[0];
    float*       out = (float*)d_out;
    int has_mask = (out_size >= 2 * CB_ELEMS) ? 1 : 0;

    mega_kernel<<<S, 256>>>(in, out, has_mask);
}

// round 16
// speedup vs baseline: 1.0022x; 1.0022x over previous
#include <cuda_runtime.h>
#include <math.h>
#include <stdint.h>

// Problem constants (inputs: [8192, 64] fp32)
#define S        8192
#define E        64
#define CAP      256              // floor(2.0 * 8192 / 64) = 256
#define ROW      (E * CAP)        // 16384 floats per token row
#define CB_ELEMS (S * E * CAP)    // 134,217,728
#define NCHUNK   (S / 32)         // 256 chunks of 32 tokens (warp-ballot grain)
#define RBLOCKS  32               // routing blocks, 256 tokens each

// -------- allocation-free scratch (device globals) --------
__device__ int   g_top1[S];
__device__ int   g_top2[S];
__device__ float g_w1[S];
__device__ float g_w2[S];
__device__ int   g_hist1[NCHUNK * E];
__device__ int   g_hist2[NCHUNK * E];
__device__ int   g_off1[NCHUNK * E];   // exclusive cumsum over chunks
__device__ int   g_off2[NCHUNK * E];
__device__ int   g_total1[E];
__device__ int   g_done;               // routing blocks completed
__device__ volatile int g_flag;        // scan results ready
__device__ int   g_exit;               // blocks past their spin (for reset)

// ---------------------------------------------------------------------------
// Single fused kernel. grid = S blocks x 256 threads.
//  Phase A (bid < 32): thread-per-token routing (softmax + top1/top2, argmax
//    tie-break = first index) + per-warp (=32-token chunk) histograms. The
//    last routing block performs the per-expert exclusive scan and releases
//    g_flag.
//  Phase B (all blocks): stream zeros over own token row, spin on g_flag
//    (already set by then), ballot-rank + patch the <=2 nonzeros.
//  Exit: last block past the spin resets flag state for the next replay.
// ---------------------------------------------------------------------------
__global__ void __launch_bounds__(256) mega_kernel(const float* __restrict__ in,
                                                   float* __restrict__ out,
                                                   int has_mask) {
    const int tid = threadIdx.x;
    const int bid = blockIdx.x;

    // ================= Phase A: routing + hist + scan =================
    if (bid < RBLOCKS) {
        __shared__ int h1[8 * E];
        __shared__ int h2[8 * E];
        for (int i = tid; i < 8 * E; i += 256) { h1[i] = 0; h2[i] = 0; }
        __syncthreads();

        const int tok = bid * 256 + tid;
        const float4* r4 = (const float4*)(in + (size_t)tok * E);

        // pass 1: online top-2 (strict > keeps first occurrence, matching
        // jnp.argmax; a duplicate of the max lands in slot 2 — also correct)
        float v1 = -INFINITY, v2 = -INFINITY;
        int   i1 = 0,         i2 = 0;
#pragma unroll
        for (int i = 0; i < 16; i++) {
            float4 v = r4[i];
            float vv[4] = {v.x, v.y, v.z, v.w};
#pragma unroll
            for (int k = 0; k < 4; k++) {
                float x = vv[k]; int j = 4 * i + k;
                if (x > v1)      { v2 = v1; i2 = i1; v1 = x; i1 = j; }
                else if (x > v2) { v2 = x;  i2 = j; }
            }
        }
        // pass 2: softmax denominator (row is 256B, L1-hot on reload)
        float sum = 0.f;
#pragma unroll
        for (int i = 0; i < 16; i++) {
            float4 v = r4[i];
            sum += expf(v.x - v1) + expf(v.y - v1)
                 + expf(v.z - v1) + expf(v.w - v1);
        }

        g_top1[tok] = i1;
        g_top2[tok] = i2;
        g_w1[tok]   = 1.0f / sum;
        g_w2[tok]   = expf(v2 - v1) / sum;

        // per-warp (= per-32-token-chunk) histogram
        int wid = tid >> 5;
        atomicAdd(&h1[wid * E + i1], 1);
        atomicAdd(&h2[wid * E + i2], 1);
        __syncthreads();
        for (int i = tid; i < 8 * E; i += 256) {
            g_hist1[(size_t)bid * 8 * E + i] = h1[i];
            g_hist2[(size_t)bid * 8 * E + i] = h2[i];
        }
        __threadfence();
        __syncthreads();

        __shared__ int lastflag;
        if (tid == 0) lastflag = (atomicAdd(&g_done, 1) == RBLOCKS - 1);
        __syncthreads();

        if (lastflag) {           // last routing block: per-expert scan
            if (tid < E) {
                const int e = tid;
                int r1 = 0, r2 = 0;
                for (int c = 0; c < NCHUNK; c++) {
                    g_off1[c * E + e] = r1;  r1 += g_hist1[c * E + e];
                    g_off2[c * E + e] = r2;  r2 += g_hist2[c * E + e];
                }
                g_total1[e] = r1;
            }
            __syncthreads();
            __threadfence();
            if (tid == 0) { g_done = 0; g_flag = 1; }   // release
        }
    }

    // ================= Phase B: zero own row =================
    const int tok = bid;
    size_t wbase = (size_t)tok * ROW;
    float4* w4 = (float4*)(out + wbase);
    float4* m4 = (float4*)(out + (size_t)CB_ELEMS + wbase);
    const float4 z = make_float4(0.f, 0.f, 0.f, 0.f);

    if (has_mask) {
#pragma unroll
        for (int i = 0; i < ROW / 4 / 256; i++) {       // 16 iters
            __stcs(&w4[i * 256 + tid], z);
            __stcs(&m4[i * 256 + tid], z);
        }
    } else {
#pragma unroll
        for (int i = 0; i < ROW / 4 / 256; i++)
            __stcs(&w4[i * 256 + tid], z);
    }

    // ---- acquire scan results (flag is set ~8us in; zeroing wave ~18us) ----
    if (tid == 0) { while (g_flag == 0) { } }
    __syncthreads();        // also orders the zeros before the patch below
    __threadfence();

    // ================= patch <=2 nonzeros (warp 0) =================
    if (tid < 32) {
        int lane  = tid;
        int chunk = tok >> 5;
        int tpos  = tok & 31;
        unsigned ltmask = (1u << tpos) - 1u;

        int t1 = g_top1[(chunk << 5) + lane];
        int t2 = g_top2[(chunk << 5) + lane];
        int e1 = __shfl_sync(0xffffffffu, t1, tpos);
        int e2 = __shfl_sync(0xffffffffu, t2, tpos);

        unsigned m1 = __ballot_sync(0xffffffffu, t1 == e1);
        unsigned m2 = __ballot_sync(0xffffffffu, t2 == e2);

        if (lane == 0) {
            int r1 = g_off1[chunk * E + e1] + __popc(m1 & ltmask);
            int r2 = g_total1[e2] + g_off2[chunk * E + e2] + __popc(m2 & ltmask);
            if (r1 < CAP) {
                size_t o = wbase + (size_t)e1 * CAP + r1;
                out[o] = g_w1[tok];
                if (has_mask) out[(size_t)CB_ELEMS + o] = 1.0f;
            }
            if (r2 < CAP) {
                size_t o = wbase + (size_t)e2 * CAP + r2;
                out[o] = g_w2[tok];
                if (has_mask) out[(size_t)CB_ELEMS + o] = 1.0f;
            }
        }
    }

    // ================= exit: reset flag state for next replay =================
    __syncthreads();
    if (tid == 0) {
        __threadfence();
        int v = atomicAdd(&g_exit, 1);
        if (v == S - 1) {       // every block has passed its spin
            g_exit = 0;
            g_flag = 0;
        }
    }
}

// ---------------------------------------------------------------------------
extern "C" void kernel_launch(void* const* d_in, const int* in_sizes, int n_in,
                              void* d_out, int out_size) {
    const float* in  = (const float*)d_in[0];
    float*       out = (float*)d_out;
    int has_mask = (out_size >= 2 * CB_ELEMS) ? 1 : 0;

    mega_kernel<<<S, 256>>>(in, out, has_mask);
}